// round 15
// baseline (speedup 1.0000x reference)
#include <cuda_runtime.h>
#include <cuda_bf16.h>
#include <math.h>
#include <stdint.h>

// ---------------- problem constants ----------------
#define BATCH   8
#define HIMG    56
#define WIMG    56
#define CDIM    384
#define NHEADS  12
#define HDIM    32
#define WIN     7
#define NTOK    49
#define SHIFT_S 3
#define TOTWIN  512
#define MTOK    25088
#define FFNDIM  1536
#define QKVN    1152          // 3*CDIM

typedef __nv_bfloat16 bf16;

// ---------------- scratch (device globals; allocation-free) ----------------
__device__ bf16  g_xw  [MTOK * CDIM];
__device__ bf16  g_qkv [MTOK * QKVN];
__device__ bf16  g_ctx [MTOK * CDIM];
__device__ float g_h   [MTOK * CDIM];
__device__ bf16  g_ln2 [MTOK * CDIM];
__device__ bf16  g_y1  [MTOK * FFNDIM];
__device__ bf16  g_wqkv[CDIM * QKVN];   // [K][N] packed q|k|v
__device__ float g_bqkv[QKVN];
__device__ bf16  g_wp  [CDIM * CDIM];
__device__ bf16  g_w1  [CDIM * FFNDIM];
__device__ bf16  g_w2  [FFNDIM * CDIM];
// bias in mma C-fragment order: [type][head][tb(4)][lane(32)][32]
__device__ bf16  g_bias[4 * NHEADS * 4 * 32 * 32];

// windowed row r <-> original token t (same map both directions)
__device__ __forceinline__ int win_row_to_token(int r) {
    int b    = r / (HIMG * WIMG);
    int rem  = r - b * (HIMG * WIMG);
    int widx = rem / NTOK;
    int tok  = rem - widx * NTOK;
    int wi = widx >> 3, wj = widx & 7;
    int i = tok / WIN, j = tok - i * WIN;
    int sh = wi * WIN + i + SHIFT_S; if (sh >= HIMG) sh -= HIMG;
    int sw = wj * WIN + j + SHIFT_S; if (sw >= WIMG) sw -= WIMG;
    return b * (HIMG * WIMG) + sh * WIMG + sw;
}

// ---------------- fused prep: pack qkv | convert weights | bias frags ------
#define W_PROJ4 (CDIM * CDIM / 4)          // 36864
#define W_FFN4  (CDIM * FFNDIM / 4)        // 147456
#define QKV_W4  (CDIM * QKVN / 4)          // 110592
#define PREP_QKV_ITEMS  (QKV_W4 + QKVN / 4)
#define PREP_W_ITEMS    (W_PROJ4 + 2 * W_FFN4)
#define PREP_QKV_BLOCKS ((PREP_QKV_ITEMS + 255) / 256)
#define PREP_W_BLOCKS   ((PREP_W_ITEMS + 255) / 256)
#define PREP_BIAS_BLOCKS 48
#define PREP_BLOCKS (PREP_QKV_BLOCKS + PREP_W_BLOCKS + PREP_BIAS_BLOCKS)

__global__ void __launch_bounds__(256) prep_kernel(
    const float* __restrict__ qw, const float* __restrict__ kw,
    const float* __restrict__ vw, const float* __restrict__ qb,
    const float* __restrict__ kb, const float* __restrict__ vb,
    bf16* __restrict__ wqkv, float* __restrict__ bqkv,
    const float* __restrict__ pw, bf16* __restrict__ wp,
    const float* __restrict__ w1s, bf16* __restrict__ w1,
    const float* __restrict__ w2s, bf16* __restrict__ w2,
    const float* __restrict__ rpb, const int* __restrict__ rpi,
    bf16* __restrict__ bias_out)
{
    int blk = blockIdx.x;
    if (blk < PREP_QKV_BLOCKS) {
        int i = blk * 256 + threadIdx.x;
        if (i < QKV_W4) {
            int row = i / (QKVN / 4);
            int col = (i % (QKVN / 4)) * 4;
            const float* src = (col < CDIM) ? qw : (col < 2 * CDIM ? kw : vw);
            int c = col - (col < CDIM ? 0 : (col < 2 * CDIM ? CDIM : 2 * CDIM));
            float4 v = *(const float4*)(src + (size_t)row * CDIM + c);
            bf16 o[4] = {__float2bfloat16(v.x), __float2bfloat16(v.y),
                         __float2bfloat16(v.z), __float2bfloat16(v.w)};
            *(uint64_t*)(wqkv + (size_t)i * 4) = *(uint64_t*)o;
        } else if (i < PREP_QKV_ITEMS) {
            int col = (i - QKV_W4) * 4;
            const float* src = (col < CDIM) ? qb : (col < 2 * CDIM ? kb : vb);
            int c = col - (col < CDIM ? 0 : (col < 2 * CDIM ? CDIM : 2 * CDIM));
            *(float4*)(bqkv + col) = *(const float4*)(src + c);
        }
    } else if (blk < PREP_QKV_BLOCKS + PREP_W_BLOCKS) {
        int i = (blk - PREP_QKV_BLOCKS) * 256 + threadIdx.x;
        const float* src; bf16* dst; int idx;
        if (i < W_PROJ4)                 { src = pw;  dst = wp; idx = i; }
        else if (i < W_PROJ4 + W_FFN4)   { src = w1s; dst = w1; idx = i - W_PROJ4; }
        else if (i < PREP_W_ITEMS)       { src = w2s; dst = w2; idx = i - W_PROJ4 - W_FFN4; }
        else return;
        float4 v = ((const float4*)src)[idx];
        bf16 o[4] = {__float2bfloat16(v.x), __float2bfloat16(v.y),
                     __float2bfloat16(v.z), __float2bfloat16(v.w)};
        *(uint64_t*)(dst + (size_t)idx * 4) = *(uint64_t*)o;
    } else {
        int bb = blk - PREP_QKV_BLOCKS - PREP_W_BLOCKS;   // 0..47
        int type = bb / NHEADS, h = bb % NHEADS;
        for (int idx = threadIdx.x; idx < 4096; idx += 256) {
            int tb   = idx >> 10;          // 0..3  (16-row tile block)
            int rem  = idx & 1023;
            int lane = rem >> 5;           // 0..31
            int j    = rem & 31;           // 0..31 (value slot)
            int nt  = j >> 2, sub = j & 3;
            int qr = lane >> 2, qc = lane & 3;
            int n = tb * 16 + qr + ((sub & 2) ? 8 : 0);
            int m = (nt >> 1) * 16 + (nt & 1) * 8 + qc * 2 + (sub & 1);
            float v;
            if (m >= 49)      v = -1e30f;
            else if (n >= 49) v = 0.f;
            else {
                v = rpb[rpi[n * 49 + m] * NHEADS + h];
                int ni = n / 7, nj = n % 7, mi = m / 7, mj = m % 7;
                int cn = ((type & 2) ? (ni < 4 ? 1 : 2) : 0) * 3 + ((type & 1) ? (nj < 4 ? 1 : 2) : 0);
                int cm = ((type & 2) ? (mi < 4 ? 1 : 2) : 0) * 3 + ((type & 1) ? (mj < 4 ? 1 : 2) : 0);
                if (cn != cm) v -= 100.0f;
            }
            bias_out[(((size_t)type * NHEADS + h) * 4096) + idx] = __float2bfloat16(v);
        }
    }
}

// ---------------- LayerNorm: warp-per-row, no barriers ----------------
__global__ void __launch_bounds__(256) ln_kernel(
    const float* __restrict__ x, const float* __restrict__ g,
    const float* __restrict__ b, bf16* __restrict__ out, int permute)
{
    int r = blockIdx.x * 8 + (threadIdx.x >> 5);
    int lane = threadIdx.x & 31;
    int t = permute ? win_row_to_token(r) : r;
    const float4* xi = (const float4*)(x + (size_t)t * CDIM);

    float4 v[3];
    float s = 0.f, ss = 0.f;
#pragma unroll
    for (int j = 0; j < 3; j++) {
        v[j] = xi[lane + 32 * j];
        s  += v[j].x + v[j].y + v[j].z + v[j].w;
        ss += v[j].x * v[j].x + v[j].y * v[j].y
            + v[j].z * v[j].z + v[j].w * v[j].w;
    }
#pragma unroll
    for (int o = 16; o; o >>= 1) {
        s  += __shfl_xor_sync(0xffffffffu, s,  o);
        ss += __shfl_xor_sync(0xffffffffu, ss, o);
    }
    float mu = s * (1.0f / CDIM);
    float var = ss * (1.0f / CDIM) - mu * mu;
    float rstd = rsqrtf(var + 1e-5f);

    bf16* yo = out + (size_t)r * CDIM;
#pragma unroll
    for (int j = 0; j < 3; j++) {
        int c = (lane + 32 * j) * 4;
        float4 gg = *(const float4*)(g + c);
        float4 bb = *(const float4*)(b + c);
        bf16 o[4];
        o[0] = __float2bfloat16((v[j].x - mu) * rstd * gg.x + bb.x);
        o[1] = __float2bfloat16((v[j].y - mu) * rstd * gg.y + bb.y);
        o[2] = __float2bfloat16((v[j].z - mu) * rstd * gg.z + bb.z);
        o[3] = __float2bfloat16((v[j].w - mu) * rstd * gg.w + bb.w);
        *(uint64_t*)(yo + c) = *(uint64_t*)o;
    }
}

// ---------------- mma helpers ----------------
#define CP16(dst, src) \
    asm volatile("cp.async.ca.shared.global [%0], [%1], 16;\n" :: \
        "r"((uint32_t)__cvta_generic_to_shared(dst)), "l"(src))
#define CP16CG(dst, src) \
    asm volatile("cp.async.cg.shared.global [%0], [%1], 16;\n" :: \
        "r"((uint32_t)__cvta_generic_to_shared(dst)), "l"(src))
#define CP_COMMIT()  asm volatile("cp.async.commit_group;\n" ::)
#define CP_WAIT(n)   asm volatile("cp.async.wait_group %0;\n" :: "n"(n))

__device__ __forceinline__ void ldm_x4(uint32_t* r, const void* p) {
    uint32_t a = (uint32_t)__cvta_generic_to_shared(p);
    asm volatile("ldmatrix.sync.aligned.m8n8.x4.shared.b16 {%0,%1,%2,%3},[%4];"
        : "=r"(r[0]), "=r"(r[1]), "=r"(r[2]), "=r"(r[3]) : "r"(a));
}
__device__ __forceinline__ void ldm_x4t(uint32_t* r, const void* p) {
    uint32_t a = (uint32_t)__cvta_generic_to_shared(p);
    asm volatile("ldmatrix.sync.aligned.m8n8.x4.trans.shared.b16 {%0,%1,%2,%3},[%4];"
        : "=r"(r[0]), "=r"(r[1]), "=r"(r[2]), "=r"(r[3]) : "r"(a));
}
#define MMA16816(d, a, b0, b1) \
    asm volatile("mma.sync.aligned.m16n8k16.row.col.f32.bf16.bf16.f32 " \
        "{%0,%1,%2,%3},{%4,%5,%6,%7},{%8,%9},{%0,%1,%2,%3};" \
        : "+f"(d[0]), "+f"(d[1]), "+f"(d[2]), "+f"(d[3]) \
        : "r"(a[0]), "r"(a[1]), "r"(a[2]), "r"(a[3]), "r"(b0), "r"(b1))

__device__ __forceinline__ uint32_t packbf(float lo, float hi) {
    __nv_bfloat162 h = __floats2bfloat162_rn(lo, hi);
    return *(uint32_t*)&h;
}

// ---------------- HMMA bf16 GEMM, 128x128x32, 5-stage, XOR-swizzled --------
// EPI 0: store  1: exact GELU  2: scatter+residual  3: residual
#define GBM 128
#define GBN 128
#define GBK 32
#define NSTG 5
#define STG_A (GBM * GBK)
#define STG_B (GBK * GBN)
#define TCSMEM (NSTG * (STG_A + STG_B) * 2)   // 81920 bytes

template <int EPI, typename OutT>
__global__ void __launch_bounds__(256) mma_gemm(
    const bf16* __restrict__ A, const bf16* __restrict__ B,
    const float* __restrict__ bias, const float* __restrict__ add,
    OutT* __restrict__ C, int M, int N, int K)
{
    extern __shared__ __align__(16) bf16 sm[];
    bf16* As = sm;
    bf16* Bs = sm + NSTG * STG_A;

    int t = threadIdx.x;
    int m0 = blockIdx.y * GBM, n0 = blockIdx.x * GBN;

    int ar = t >> 2, acw = t & 3;
    int br = t >> 3, bcw = (t & 7) * 2;
    const bf16* Ag = A + (size_t)(m0 + ar) * K + acw * 8;
    const bf16* Bg = B + (size_t)br * N + n0 + bcw * 8;

    int aswz = (ar >> 1) & 3;
    int a_off0 = ar * 32 + ((acw ^ aswz) << 3);
    int a_off1 = (ar + 64) * 32 + ((acw ^ aswz) << 3);
    int b_off0 = br * 128 + (((bcw)     ^ (br & 7)) << 3);
    int b_off1 = br * 128 + (((bcw + 1) ^ (br & 7)) << 3);

    int lane = t & 31, w = t >> 5;
    int m0w = (w >> 1) * 32, nw = (w & 1) * 64;
    int lrow = (lane & 7) + (lane & 8);
    int lcol = (lane & 16) >> 1;

    float acc[2][8][4] = {};

    int nk = K / GBK;
#pragma unroll
    for (int s = 0; s < NSTG - 1; s++) {
        int k0 = s * GBK;
        CP16CG(&As[s * STG_A + a_off0], Ag + k0);
        CP16CG(&As[s * STG_A + a_off1], Ag + (size_t)64 * K + k0);
        CP16CG(&Bs[s * STG_B + b_off0], Bg + (size_t)k0 * N);
        CP16CG(&Bs[s * STG_B + b_off1], Bg + (size_t)k0 * N + 8);
        CP_COMMIT();
    }

    for (int i = 0; i < nk; i++) {
        if (i + 3 < nk)      { CP_WAIT(3); }
        else if (i + 2 < nk) { CP_WAIT(2); }
        else if (i + 1 < nk) { CP_WAIT(1); }
        else                 { CP_WAIT(0); }
        __syncthreads();
        if (i + NSTG - 1 < nk) {
            int st = (i + NSTG - 1) % NSTG;
            int k0 = (i + NSTG - 1) * GBK;
            CP16CG(&As[st * STG_A + a_off0], Ag + k0);
            CP16CG(&As[st * STG_A + a_off1], Ag + (size_t)64 * K + k0);
            CP16CG(&Bs[st * STG_B + b_off0], Bg + (size_t)k0 * N);
            CP16CG(&Bs[st * STG_B + b_off1], Bg + (size_t)k0 * N + 8);
            CP_COMMIT();
        }
        int cs = i % NSTG;
        const bf16* Asc = As + cs * STG_A;
        const bf16* Bsc = Bs + cs * STG_B;
#pragma unroll
        for (int kk = 0; kk < GBK; kk += 16) {
            uint32_t a[2][4], b[4][4];
#pragma unroll
            for (int mi = 0; mi < 2; mi++) {
                int R = m0w + mi * 16 + lrow;
                int cr = (kk + lcol) >> 3;
                ldm_x4(a[mi], Asc + R * 32 + ((cr ^ ((R >> 1) & 3)) << 3));
            }
#pragma unroll
            for (int nj = 0; nj < 4; nj++) {
                int Kr = kk + lrow;
                int cn = (nw + nj * 16 + lcol) >> 3;
                ldm_x4t(b[nj], Bsc + Kr * 128 + ((cn ^ (Kr & 7)) << 3));
            }
#pragma unroll
            for (int mi = 0; mi < 2; mi++) {
#pragma unroll
                for (int nt = 0; nt < 8; nt++)
                    MMA16816(acc[mi][nt], a[mi],
                             b[nt >> 1][(nt & 1) * 2], b[nt >> 1][(nt & 1) * 2 + 1]);
            }
        }
    }

#pragma unroll
    for (int mi = 0; mi < 2; mi++) {
        int rbase = m0 + m0w + mi * 16 + (lane >> 2);
#pragma unroll
        for (int h2 = 0; h2 < 2; h2++) {
            int row = rbase + 8 * h2;
            int orow = (EPI == 2) ? win_row_to_token(row) : row;
#pragma unroll
            for (int nt = 0; nt < 8; nt++) {
                int col = n0 + nw + nt * 8 + (lane & 3) * 2;
                float v0 = acc[mi][nt][2 * h2 + 0] + bias[col];
                float v1 = acc[mi][nt][2 * h2 + 1] + bias[col + 1];
                if (EPI == 1) {
                    v0 = 0.5f * v0 * (1.0f + erff(v0 * 0.7071067811865475f));
                    v1 = 0.5f * v1 * (1.0f + erff(v1 * 0.7071067811865475f));
                } else if (EPI == 2 || EPI == 3) {
                    const float* ap = add + (size_t)orow * N + col;
                    v0 += ap[0];
                    v1 += ap[1];
                }
                OutT* cp = C + (size_t)orow * N + col;
                if (sizeof(OutT) == 2) {
                    __nv_bfloat162 pk;
                    pk.x = __float2bfloat16(v0);
                    pk.y = __float2bfloat16(v1);
                    *(__nv_bfloat162*)cp = pk;
                } else {
                    float2 pk = make_float2(v0, v1);
                    *(float2*)cp = pk;
                }
            }
        }
    }
}

// ---------------- tensor-core window attention ----------------
// grid (TOTWIN, 6). Bias pre-swizzled to fragment order; 4 coalesced uint4
// loads per thread replace the smem bias staging. 4 CTAs/SM.
__global__ void __launch_bounds__(256, 4) attn_mma_kernel(
    const bf16* __restrict__ QKV, const bf16* __restrict__ bias_all,
    bf16* __restrict__ O)
{
    __shared__ __align__(16) bf16 sQ[2][64][40];
    __shared__ __align__(16) bf16 sK[2][64][40];
    __shared__ __align__(16) bf16 sV[2][64][40];

    int win = blockIdx.x, p = blockIdx.y, t = threadIdx.x;
    int widx = win & 63;
    int type = (((widx >> 3) == 7) ? 2 : 0) + (((widx & 7) == 7) ? 1 : 0);

    int lane = t & 31, w = t >> 5;
    int hs = w >> 2, ww = w & 3;
    int r0 = ww * 16;
    int lrow = (lane & 7) + (lane & 8);
    int lcol = (lane & 16) >> 1;
    int qr = lane >> 2, qc = lane & 3;
    const float scale = 0.17677669529663687f;

    int lr = t >> 2, lc = t & 3;

    // issue QKV loads
    if (lr < 49) {
        const bf16* src = QKV + (size_t)(win * NTOK + lr) * QKVN + lc * 8;
#pragma unroll
        for (int hh = 0; hh < 2; hh++) {
            int h = p * 2 + hh;
            CP16CG(&sQ[hh][lr][lc * 8], src + h * HDIM);
            CP16CG(&sK[hh][lr][lc * 8], src + h * HDIM + CDIM);
            CP16CG(&sV[hh][lr][lc * 8], src + h * HDIM + 2 * CDIM);
        }
    }
    CP_COMMIT();

    // zero K,V pad rows (49..63) while loads are in flight
    for (int i = t; i < 2 * 15 * 40; i += 256) {
        int hz = i / 600, rem = i % 600;
        int row = 49 + rem / 40, col = rem % 40;
        sK[hz][row][col] = __float2bfloat16(0.f);
        sV[hz][row][col] = __float2bfloat16(0.f);
    }

    CP_WAIT(0);
    __syncthreads();

    // S = Q K^T
    float acc[8][4] = {};
#pragma unroll
    for (int kc = 0; kc < 32; kc += 16) {
        uint32_t a[4];
        ldm_x4(a, &sQ[hs][r0 + lrow][kc + lcol]);
        uint32_t bb[4][4];
#pragma unroll
        for (int nj = 0; nj < 4; nj++)
            ldm_x4(bb[nj], &sK[hs][nj * 16 + lrow][kc + lcol]);
#pragma unroll
        for (int nj = 0; nj < 4; nj++) {
            MMA16816(acc[nj * 2 + 0], a, bb[nj][0], bb[nj][2]);
            MMA16816(acc[nj * 2 + 1], a, bb[nj][1], bb[nj][3]);
        }
    }

    // scale + bias (fragment-order, 4 coalesced uint4 loads)
    int H = p * 2 + hs;
    {
        const uint4* bp = (const uint4*)(bias_all +
            ((((size_t)type * NHEADS + H) * 4 + ww) * 32 + lane) * 32);
        uint4 q0 = bp[0], q1 = bp[1], q2 = bp[2], q3 = bp[3];
        bf16 barr[32];
        ((uint4*)barr)[0] = q0; ((uint4*)barr)[1] = q1;
        ((uint4*)barr)[2] = q2; ((uint4*)barr)[3] = q3;
#pragma unroll
        for (int nt = 0; nt < 8; nt++) {
#pragma unroll
            for (int sub = 0; sub < 4; sub++)
                acc[nt][sub] = acc[nt][sub] * scale
                             + __bfloat162float(barr[nt * 4 + sub]);
        }
    }

    // softmax
    float mx1 = -1e30f, mx2 = -1e30f;
#pragma unroll
    for (int nt = 0; nt < 8; nt++) {
        mx1 = fmaxf(mx1, fmaxf(acc[nt][0], acc[nt][1]));
        mx2 = fmaxf(mx2, fmaxf(acc[nt][2], acc[nt][3]));
    }
    mx1 = fmaxf(mx1, __shfl_xor_sync(0xffffffffu, mx1, 1));
    mx1 = fmaxf(mx1, __shfl_xor_sync(0xffffffffu, mx1, 2));
    mx2 = fmaxf(mx2, __shfl_xor_sync(0xffffffffu, mx2, 1));
    mx2 = fmaxf(mx2, __shfl_xor_sync(0xffffffffu, mx2, 2));
    float sum1 = 0.f, sum2 = 0.f;
#pragma unroll
    for (int nt = 0; nt < 8; nt++) {
        acc[nt][0] = __expf(acc[nt][0] - mx1);
        acc[nt][1] = __expf(acc[nt][1] - mx1);
        acc[nt][2] = __expf(acc[nt][2] - mx2);
        acc[nt][3] = __expf(acc[nt][3] - mx2);
        sum1 += acc[nt][0] + acc[nt][1];
        sum2 += acc[nt][2] + acc[nt][3];
    }
    sum1 += __shfl_xor_sync(0xffffffffu, sum1, 1);
    sum1 += __shfl_xor_sync(0xffffffffu, sum1, 2);
    sum2 += __shfl_xor_sync(0xffffffffu, sum2, 1);
    sum2 += __shfl_xor_sync(0xffffffffu, sum2, 2);
    float inv1 = 1.0f / sum1, inv2 = 1.0f / sum2;

    // ctx = P V
    float o[4][4] = {};
#pragma unroll
    for (int kc2 = 0; kc2 < 4; kc2++) {
        uint32_t pa[4];
        pa[0] = packbf(acc[2 * kc2][0],     acc[2 * kc2][1]);
        pa[1] = packbf(acc[2 * kc2][2],     acc[2 * kc2][3]);
        pa[2] = packbf(acc[2 * kc2 + 1][0], acc[2 * kc2 + 1][1]);
        pa[3] = packbf(acc[2 * kc2 + 1][2], acc[2 * kc2 + 1][3]);
#pragma unroll
        for (int nj = 0; nj < 2; nj++) {
            uint32_t vb[4];
            ldm_x4t(vb, &sV[hs][kc2 * 16 + lrow][nj * 16 + lcol]);
            MMA16816(o[nj * 2 + 0], pa, vb[0], vb[1]);
            MMA16816(o[nj * 2 + 1], pa, vb[2], vb[3]);
        }
    }
    int row1 = r0 + qr, row2 = r0 + qr + 8;
    if (row1 < NTOK) {
        bf16* dst = O + (size_t)(win * NTOK + row1) * CDIM + H * HDIM + qc * 2;
#pragma unroll
        for (int nt = 0; nt < 4; nt++) {
            __nv_bfloat162 pk;
            pk.x = __float2bfloat16(o[nt][0] * inv1);
            pk.y = __float2bfloat16(o[nt][1] * inv1);
            *(__nv_bfloat162*)(dst + nt * 8) = pk;
        }
    }
    if (row2 < NTOK) {
        bf16* dst = O + (size_t)(win * NTOK + row2) * CDIM + H * HDIM + qc * 2;
#pragma unroll
        for (int nt = 0; nt < 4; nt++) {
            __nv_bfloat162 pk;
            pk.x = __float2bfloat16(o[nt][2] * inv2);
            pk.y = __float2bfloat16(o[nt][3] * inv2);
            *(__nv_bfloat162*)(dst + nt * 8) = pk;
        }
    }
}

// ---------------- launch ----------------
extern "C" void kernel_launch(void* const* d_in, const int* in_sizes, int n_in,
                              void* d_out, int out_size)
{
    const float* hidden  = (const float*)d_in[0];
    const float* ln1_g   = (const float*)d_in[1];
    const float* ln1_b   = (const float*)d_in[2];
    const float* q_w     = (const float*)d_in[3];
    const float* q_b     = (const float*)d_in[4];
    const float* k_w     = (const float*)d_in[5];
    const float* k_b     = (const float*)d_in[6];
    const float* v_w     = (const float*)d_in[7];
    const float* v_b     = (const float*)d_in[8];
    const float* rpb     = (const float*)d_in[9];
    const int*   rpi     = (const int*)  d_in[10];
    const float* proj_w  = (const float*)d_in[11];
    const float* proj_b  = (const float*)d_in[12];
    const float* ln2_g   = (const float*)d_in[13];
    const float* ln2_b   = (const float*)d_in[14];
    const float* fc1_w   = (const float*)d_in[15];
    const float* fc1_b   = (const float*)d_in[16];
    const float* fc2_w   = (const float*)d_in[17];
    const float* fc2_b   = (const float*)d_in[18];
    float* out = (float*)d_out;

    bf16 *p_xw, *p_qkv, *p_ctx, *p_ln2, *p_y1;
    bf16 *p_wqkv, *p_wp, *p_w1, *p_w2, *p_bias;
    float *p_h, *p_bqkv;
    cudaGetSymbolAddress((void**)&p_xw,   g_xw);
    cudaGetSymbolAddress((void**)&p_qkv,  g_qkv);
    cudaGetSymbolAddress((void**)&p_ctx,  g_ctx);
    cudaGetSymbolAddress((void**)&p_h,    g_h);
    cudaGetSymbolAddress((void**)&p_ln2,  g_ln2);
    cudaGetSymbolAddress((void**)&p_y1,   g_y1);
    cudaGetSymbolAddress((void**)&p_wqkv, g_wqkv);
    cudaGetSymbolAddress((void**)&p_bqkv, g_bqkv);
    cudaGetSymbolAddress((void**)&p_wp,   g_wp);
    cudaGetSymbolAddress((void**)&p_w1,   g_w1);
    cudaGetSymbolAddress((void**)&p_w2,   g_w2);
    cudaGetSymbolAddress((void**)&p_bias, g_bias);

    cudaFuncSetAttribute(mma_gemm<0, bf16>,  cudaFuncAttributeMaxDynamicSharedMemorySize, TCSMEM);
    cudaFuncSetAttribute(mma_gemm<1, bf16>,  cudaFuncAttributeMaxDynamicSharedMemorySize, TCSMEM);
    cudaFuncSetAttribute(mma_gemm<2, float>, cudaFuncAttributeMaxDynamicSharedMemorySize, TCSMEM);
    cudaFuncSetAttribute(mma_gemm<3, float>, cudaFuncAttributeMaxDynamicSharedMemorySize, TCSMEM);

    // 0) fused prep: pack qkv + convert weights + bias fragments
    prep_kernel<<<PREP_BLOCKS, 256>>>(
        q_w, k_w, v_w, q_b, k_b, v_b, p_wqkv, p_bqkv,
        proj_w, p_wp, fc1_w, p_w1, fc2_w, p_w2,
        rpb, rpi, p_bias);

    // 1) LN1 + shift-roll + window partition (gather)
    ln_kernel<<<MTOK / 8, 256>>>(hidden, ln1_g, ln1_b, p_xw, 1);

    // 2) fused QKV projection
    mma_gemm<0, bf16><<<dim3(QKVN / GBN, MTOK / GBM), 256, TCSMEM>>>(
        p_xw, p_wqkv, p_bqkv, nullptr, p_qkv, MTOK, QKVN, CDIM);

    // 3) windowed attention (one block per window x head-pair)
    attn_mma_kernel<<<dim3(TOTWIN, NHEADS / 2), 256>>>(p_qkv, p_bias, p_ctx);

    // 4) output projection + window-reverse + roll-back + residual (scatter)
    mma_gemm<2, float><<<dim3(CDIM / GBN, MTOK / GBM), 256, TCSMEM>>>(
        p_ctx, p_wp, proj_b, hidden, p_h, MTOK, CDIM, CDIM);

    // 5) LN2
    ln_kernel<<<MTOK / 8, 256>>>(p_h, ln2_g, ln2_b, p_ln2, 0);

    // 6) fc1 + exact GELU
    mma_gemm<1, bf16><<<dim3(FFNDIM / GBN, MTOK / GBM), 256, TCSMEM>>>(
        p_ln2, p_w1, fc1_b, nullptr, p_y1, MTOK, FFNDIM, CDIM);

    // 7) fc2 + residual -> final output
    mma_gemm<3, float><<<dim3(CDIM / GBN, MTOK / GBM), 256, TCSMEM>>>(
        p_y1, p_w2, fc2_b, p_h, out, MTOK, CDIM, FFNDIM);
}

// round 16
// speedup vs baseline: 1.0036x; 1.0036x over previous
#include <cuda_runtime.h>
#include <cuda_bf16.h>
#include <math.h>
#include <stdint.h>

// ---------------- problem constants ----------------
#define BATCH   8
#define HIMG    56
#define WIMG    56
#define CDIM    384
#define NHEADS  12
#define HDIM    32
#define WIN     7
#define NTOK    49
#define SHIFT_S 3
#define TOTWIN  512
#define MTOK    25088
#define FFNDIM  1536
#define QKVN    1152          // 3*CDIM

typedef __nv_bfloat16 bf16;

// ---------------- scratch (device globals; allocation-free) ----------------
__device__ bf16  g_xw  [MTOK * CDIM];
__device__ bf16  g_qkv [MTOK * QKVN];
__device__ bf16  g_ctx [MTOK * CDIM];
__device__ float g_h   [MTOK * CDIM];
__device__ bf16  g_ln2 [MTOK * CDIM];
__device__ bf16  g_y1  [MTOK * FFNDIM];
__device__ bf16  g_wqkv[CDIM * QKVN];   // [K][N] packed q|k|v
__device__ float g_bqkv[QKVN];
__device__ bf16  g_wp  [CDIM * CDIM];
__device__ bf16  g_w1  [CDIM * FFNDIM];
__device__ bf16  g_w2  [FFNDIM * CDIM];
// bias in mma C-fragment order: [type][head][tb(4)][lane(32)][32]
__device__ bf16  g_bias[4 * NHEADS * 4 * 32 * 32];

// windowed row r <-> original token t (same map both directions)
__device__ __forceinline__ int win_row_to_token(int r) {
    int b    = r / (HIMG * WIMG);
    int rem  = r - b * (HIMG * WIMG);
    int widx = rem / NTOK;
    int tok  = rem - widx * NTOK;
    int wi = widx >> 3, wj = widx & 7;
    int i = tok / WIN, j = tok - i * WIN;
    int sh = wi * WIN + i + SHIFT_S; if (sh >= HIMG) sh -= HIMG;
    int sw = wj * WIN + j + SHIFT_S; if (sw >= WIMG) sw -= WIMG;
    return b * (HIMG * WIMG) + sh * WIMG + sw;
}

// ---------------- fused prep: pack qkv | convert weights | bias frags ------
#define W_PROJ4 (CDIM * CDIM / 4)          // 36864
#define W_FFN4  (CDIM * FFNDIM / 4)        // 147456
#define QKV_W4  (CDIM * QKVN / 4)          // 110592
#define PREP_QKV_ITEMS  (QKV_W4 + QKVN / 4)
#define PREP_W_ITEMS    (W_PROJ4 + 2 * W_FFN4)
#define PREP_QKV_BLOCKS ((PREP_QKV_ITEMS + 255) / 256)
#define PREP_W_BLOCKS   ((PREP_W_ITEMS + 255) / 256)
#define PREP_BIAS_BLOCKS 48
#define PREP_BLOCKS (PREP_QKV_BLOCKS + PREP_W_BLOCKS + PREP_BIAS_BLOCKS)

__global__ void __launch_bounds__(256) prep_kernel(
    const float* __restrict__ qw, const float* __restrict__ kw,
    const float* __restrict__ vw, const float* __restrict__ qb,
    const float* __restrict__ kb, const float* __restrict__ vb,
    bf16* __restrict__ wqkv, float* __restrict__ bqkv,
    const float* __restrict__ pw, bf16* __restrict__ wp,
    const float* __restrict__ w1s, bf16* __restrict__ w1,
    const float* __restrict__ w2s, bf16* __restrict__ w2,
    const float* __restrict__ rpb, const int* __restrict__ rpi,
    bf16* __restrict__ bias_out)
{
    int blk = blockIdx.x;
    if (blk < PREP_QKV_BLOCKS) {
        int i = blk * 256 + threadIdx.x;
        if (i < QKV_W4) {
            int row = i / (QKVN / 4);
            int col = (i % (QKVN / 4)) * 4;
            const float* src = (col < CDIM) ? qw : (col < 2 * CDIM ? kw : vw);
            int c = col - (col < CDIM ? 0 : (col < 2 * CDIM ? CDIM : 2 * CDIM));
            float4 v = *(const float4*)(src + (size_t)row * CDIM + c);
            bf16 o[4] = {__float2bfloat16(v.x), __float2bfloat16(v.y),
                         __float2bfloat16(v.z), __float2bfloat16(v.w)};
            *(uint64_t*)(wqkv + (size_t)i * 4) = *(uint64_t*)o;
        } else if (i < PREP_QKV_ITEMS) {
            int col = (i - QKV_W4) * 4;
            const float* src = (col < CDIM) ? qb : (col < 2 * CDIM ? kb : vb);
            int c = col - (col < CDIM ? 0 : (col < 2 * CDIM ? CDIM : 2 * CDIM));
            *(float4*)(bqkv + col) = *(const float4*)(src + c);
        }
    } else if (blk < PREP_QKV_BLOCKS + PREP_W_BLOCKS) {
        int i = (blk - PREP_QKV_BLOCKS) * 256 + threadIdx.x;
        const float* src; bf16* dst; int idx;
        if (i < W_PROJ4)                 { src = pw;  dst = wp; idx = i; }
        else if (i < W_PROJ4 + W_FFN4)   { src = w1s; dst = w1; idx = i - W_PROJ4; }
        else if (i < PREP_W_ITEMS)       { src = w2s; dst = w2; idx = i - W_PROJ4 - W_FFN4; }
        else return;
        float4 v = ((const float4*)src)[idx];
        bf16 o[4] = {__float2bfloat16(v.x), __float2bfloat16(v.y),
                     __float2bfloat16(v.z), __float2bfloat16(v.w)};
        *(uint64_t*)(dst + (size_t)idx * 4) = *(uint64_t*)o;
    } else {
        int bb = blk - PREP_QKV_BLOCKS - PREP_W_BLOCKS;   // 0..47
        int type = bb / NHEADS, h = bb % NHEADS;
        for (int idx = threadIdx.x; idx < 4096; idx += 256) {
            int tb   = idx >> 10;          // 0..3  (16-row tile block)
            int rem  = idx & 1023;
            int lane = rem >> 5;           // 0..31
            int j    = rem & 31;           // 0..31 (value slot)
            int nt  = j >> 2, sub = j & 3;
            int qr = lane >> 2, qc = lane & 3;
            int n = tb * 16 + qr + ((sub & 2) ? 8 : 0);
            int m = (nt >> 1) * 16 + (nt & 1) * 8 + qc * 2 + (sub & 1);
            float v;
            if (m >= 49)      v = -1e30f;
            else if (n >= 49) v = 0.f;
            else {
                v = rpb[rpi[n * 49 + m] * NHEADS + h];
                int ni = n / 7, nj = n % 7, mi = m / 7, mj = m % 7;
                int cn = ((type & 2) ? (ni < 4 ? 1 : 2) : 0) * 3 + ((type & 1) ? (nj < 4 ? 1 : 2) : 0);
                int cm = ((type & 2) ? (mi < 4 ? 1 : 2) : 0) * 3 + ((type & 1) ? (mj < 4 ? 1 : 2) : 0);
                if (cn != cm) v -= 100.0f;
            }
            bias_out[(((size_t)type * NHEADS + h) * 4096) + idx] = __float2bfloat16(v);
        }
    }
}

// ---------------- LayerNorm: warp-per-row, no barriers ----------------
__global__ void __launch_bounds__(256) ln_kernel(
    const float* __restrict__ x, const float* __restrict__ g,
    const float* __restrict__ b, bf16* __restrict__ out, int permute)
{
    int r = blockIdx.x * 8 + (threadIdx.x >> 5);
    int lane = threadIdx.x & 31;
    int t = permute ? win_row_to_token(r) : r;
    const float4* xi = (const float4*)(x + (size_t)t * CDIM);

    float4 v[3];
    float s = 0.f, ss = 0.f;
#pragma unroll
    for (int j = 0; j < 3; j++) {
        v[j] = xi[lane + 32 * j];
        s  += v[j].x + v[j].y + v[j].z + v[j].w;
        ss += v[j].x * v[j].x + v[j].y * v[j].y
            + v[j].z * v[j].z + v[j].w * v[j].w;
    }
#pragma unroll
    for (int o = 16; o; o >>= 1) {
        s  += __shfl_xor_sync(0xffffffffu, s,  o);
        ss += __shfl_xor_sync(0xffffffffu, ss, o);
    }
    float mu = s * (1.0f / CDIM);
    float var = ss * (1.0f / CDIM) - mu * mu;
    float rstd = rsqrtf(var + 1e-5f);

    bf16* yo = out + (size_t)r * CDIM;
#pragma unroll
    for (int j = 0; j < 3; j++) {
        int c = (lane + 32 * j) * 4;
        float4 gg = *(const float4*)(g + c);
        float4 bb = *(const float4*)(b + c);
        bf16 o[4];
        o[0] = __float2bfloat16((v[j].x - mu) * rstd * gg.x + bb.x);
        o[1] = __float2bfloat16((v[j].y - mu) * rstd * gg.y + bb.y);
        o[2] = __float2bfloat16((v[j].z - mu) * rstd * gg.z + bb.z);
        o[3] = __float2bfloat16((v[j].w - mu) * rstd * gg.w + bb.w);
        *(uint64_t*)(yo + c) = *(uint64_t*)o;
    }
}

// ---------------- mma helpers ----------------
#define CP16(dst, src) \
    asm volatile("cp.async.ca.shared.global [%0], [%1], 16;\n" :: \
        "r"((uint32_t)__cvta_generic_to_shared(dst)), "l"(src))
#define CP16CG(dst, src) \
    asm volatile("cp.async.cg.shared.global [%0], [%1], 16;\n" :: \
        "r"((uint32_t)__cvta_generic_to_shared(dst)), "l"(src))
#define CP_COMMIT()  asm volatile("cp.async.commit_group;\n" ::)
#define CP_WAIT(n)   asm volatile("cp.async.wait_group %0;\n" :: "n"(n))

__device__ __forceinline__ void ldm_x4(uint32_t* r, const void* p) {
    uint32_t a = (uint32_t)__cvta_generic_to_shared(p);
    asm volatile("ldmatrix.sync.aligned.m8n8.x4.shared.b16 {%0,%1,%2,%3},[%4];"
        : "=r"(r[0]), "=r"(r[1]), "=r"(r[2]), "=r"(r[3]) : "r"(a));
}
__device__ __forceinline__ void ldm_x4t(uint32_t* r, const void* p) {
    uint32_t a = (uint32_t)__cvta_generic_to_shared(p);
    asm volatile("ldmatrix.sync.aligned.m8n8.x4.trans.shared.b16 {%0,%1,%2,%3},[%4];"
        : "=r"(r[0]), "=r"(r[1]), "=r"(r[2]), "=r"(r[3]) : "r"(a));
}
#define MMA16816(d, a, b0, b1) \
    asm volatile("mma.sync.aligned.m16n8k16.row.col.f32.bf16.bf16.f32 " \
        "{%0,%1,%2,%3},{%4,%5,%6,%7},{%8,%9},{%0,%1,%2,%3};" \
        : "+f"(d[0]), "+f"(d[1]), "+f"(d[2]), "+f"(d[3]) \
        : "r"(a[0]), "r"(a[1]), "r"(a[2]), "r"(a[3]), "r"(b0), "r"(b1))

__device__ __forceinline__ uint32_t packbf(float lo, float hi) {
    __nv_bfloat162 h = __floats2bfloat162_rn(lo, hi);
    return *(uint32_t*)&h;
}

// ---------------- HMMA bf16 GEMM, 128x128x32, 5-stage, XOR-swizzled --------
// EPI 0: store  1: exact GELU  2: scatter+residual  3: residual
#define GBM 128
#define GBN 128
#define GBK 32
#define NSTG 5
#define STG_A (GBM * GBK)
#define STG_B (GBK * GBN)
#define TCSMEM (NSTG * (STG_A + STG_B) * 2)   // 81920 bytes

template <int EPI, typename OutT>
__global__ void __launch_bounds__(256) mma_gemm(
    const bf16* __restrict__ A, const bf16* __restrict__ B,
    const float* __restrict__ bias, const float* __restrict__ add,
    OutT* __restrict__ C, int M, int N, int K)
{
    extern __shared__ __align__(16) bf16 sm[];
    bf16* As = sm;
    bf16* Bs = sm + NSTG * STG_A;

    int t = threadIdx.x;
    int m0 = blockIdx.y * GBM, n0 = blockIdx.x * GBN;

    int ar = t >> 2, acw = t & 3;
    int br = t >> 3, bcw = (t & 7) * 2;
    const bf16* Ag = A + (size_t)(m0 + ar) * K + acw * 8;
    const bf16* Bg = B + (size_t)br * N + n0 + bcw * 8;

    int aswz = (ar >> 1) & 3;
    int a_off0 = ar * 32 + ((acw ^ aswz) << 3);
    int a_off1 = (ar + 64) * 32 + ((acw ^ aswz) << 3);
    int b_off0 = br * 128 + (((bcw)     ^ (br & 7)) << 3);
    int b_off1 = br * 128 + (((bcw + 1) ^ (br & 7)) << 3);

    int lane = t & 31, w = t >> 5;
    int m0w = (w >> 1) * 32, nw = (w & 1) * 64;
    int lrow = (lane & 7) + (lane & 8);
    int lcol = (lane & 16) >> 1;

    float acc[2][8][4] = {};

    int nk = K / GBK;
#pragma unroll
    for (int s = 0; s < NSTG - 1; s++) {
        int k0 = s * GBK;
        CP16CG(&As[s * STG_A + a_off0], Ag + k0);
        CP16CG(&As[s * STG_A + a_off1], Ag + (size_t)64 * K + k0);
        CP16CG(&Bs[s * STG_B + b_off0], Bg + (size_t)k0 * N);
        CP16CG(&Bs[s * STG_B + b_off1], Bg + (size_t)k0 * N + 8);
        CP_COMMIT();
    }

    for (int i = 0; i < nk; i++) {
        if (i + 3 < nk)      { CP_WAIT(3); }
        else if (i + 2 < nk) { CP_WAIT(2); }
        else if (i + 1 < nk) { CP_WAIT(1); }
        else                 { CP_WAIT(0); }
        __syncthreads();
        if (i + NSTG - 1 < nk) {
            int st = (i + NSTG - 1) % NSTG;
            int k0 = (i + NSTG - 1) * GBK;
            CP16CG(&As[st * STG_A + a_off0], Ag + k0);
            CP16CG(&As[st * STG_A + a_off1], Ag + (size_t)64 * K + k0);
            CP16CG(&Bs[st * STG_B + b_off0], Bg + (size_t)k0 * N);
            CP16CG(&Bs[st * STG_B + b_off1], Bg + (size_t)k0 * N + 8);
            CP_COMMIT();
        }
        int cs = i % NSTG;
        const bf16* Asc = As + cs * STG_A;
        const bf16* Bsc = Bs + cs * STG_B;
#pragma unroll
        for (int kk = 0; kk < GBK; kk += 16) {
            uint32_t a[2][4], b[4][4];
#pragma unroll
            for (int mi = 0; mi < 2; mi++) {
                int R = m0w + mi * 16 + lrow;
                int cr = (kk + lcol) >> 3;
                ldm_x4(a[mi], Asc + R * 32 + ((cr ^ ((R >> 1) & 3)) << 3));
            }
#pragma unroll
            for (int nj = 0; nj < 4; nj++) {
                int Kr = kk + lrow;
                int cn = (nw + nj * 16 + lcol) >> 3;
                ldm_x4t(b[nj], Bsc + Kr * 128 + ((cn ^ (Kr & 7)) << 3));
            }
#pragma unroll
            for (int mi = 0; mi < 2; mi++) {
#pragma unroll
                for (int nt = 0; nt < 8; nt++)
                    MMA16816(acc[mi][nt], a[mi],
                             b[nt >> 1][(nt & 1) * 2], b[nt >> 1][(nt & 1) * 2 + 1]);
            }
        }
    }

#pragma unroll
    for (int mi = 0; mi < 2; mi++) {
        int rbase = m0 + m0w + mi * 16 + (lane >> 2);
#pragma unroll
        for (int h2 = 0; h2 < 2; h2++) {
            int row = rbase + 8 * h2;
            int orow = (EPI == 2) ? win_row_to_token(row) : row;
#pragma unroll
            for (int nt = 0; nt < 8; nt++) {
                int col = n0 + nw + nt * 8 + (lane & 3) * 2;
                float v0 = acc[mi][nt][2 * h2 + 0] + bias[col];
                float v1 = acc[mi][nt][2 * h2 + 1] + bias[col + 1];
                if (EPI == 1) {
                    v0 = 0.5f * v0 * (1.0f + erff(v0 * 0.7071067811865475f));
                    v1 = 0.5f * v1 * (1.0f + erff(v1 * 0.7071067811865475f));
                } else if (EPI == 2 || EPI == 3) {
                    const float* ap = add + (size_t)orow * N + col;
                    v0 += ap[0];
                    v1 += ap[1];
                }
                OutT* cp = C + (size_t)orow * N + col;
                if (sizeof(OutT) == 2) {
                    __nv_bfloat162 pk;
                    pk.x = __float2bfloat16(v0);
                    pk.y = __float2bfloat16(v1);
                    *(__nv_bfloat162*)cp = pk;
                } else {
                    float2 pk = make_float2(v0, v1);
                    *(float2*)cp = pk;
                }
            }
        }
    }
}

// ---------------- tensor-core window attention ----------------
// grid (TOTWIN, 12): one block per (window, head). 128 threads, 4 warps.
// Bias pre-swizzled to fragment order; 4 coalesced uint4 loads per thread.
__global__ void __launch_bounds__(128) attn_mma_kernel(
    const bf16* __restrict__ QKV, const bf16* __restrict__ bias_all,
    bf16* __restrict__ O)
{
    __shared__ __align__(16) bf16 sQ[64][40];
    __shared__ __align__(16) bf16 sK[64][40];
    __shared__ __align__(16) bf16 sV[64][40];

    int win = blockIdx.x, H = blockIdx.y, t = threadIdx.x;
    int widx = win & 63;
    int type = (((widx >> 3) == 7) ? 2 : 0) + (((widx & 7) == 7) ? 1 : 0);

    int lane = t & 31, ww = t >> 5;          // 4 warps
    int r0 = ww * 16;
    int lrow = (lane & 7) + (lane & 8);
    int lcol = (lane & 16) >> 1;
    int qr = lane >> 2, qc = lane & 3;
    const float scale = 0.17677669529663687f;

    int lr = t >> 1, lc2 = (t & 1) * 2;      // 2 threads per row, 2 chunks each

    // issue QKV loads (rows 0..63 covered by 128 threads; guard 49..63)
    if (lr < 49) {
        const bf16* src = QKV + (size_t)(win * NTOK + lr) * QKVN + H * HDIM + lc2 * 8;
        CP16CG(&sQ[lr][lc2 * 8], src);
        CP16CG(&sQ[lr][lc2 * 8 + 8], src + 8);
        CP16CG(&sK[lr][lc2 * 8], src + CDIM);
        CP16CG(&sK[lr][lc2 * 8 + 8], src + CDIM + 8);
        CP16CG(&sV[lr][lc2 * 8], src + 2 * CDIM);
        CP16CG(&sV[lr][lc2 * 8 + 8], src + 2 * CDIM + 8);
    }
    CP_COMMIT();

    // zero K,V pad rows (49..63) while loads are in flight: 15*40*2 = 1200
    for (int i = t; i < 15 * 40; i += 128) {
        int row = 49 + i / 40, col = i % 40;
        sK[row][col] = __float2bfloat16(0.f);
        sV[row][col] = __float2bfloat16(0.f);
    }

    CP_WAIT(0);
    __syncthreads();

    // S = Q K^T (16 rows per warp, 64 cols)
    float acc[8][4] = {};
#pragma unroll
    for (int kc = 0; kc < 32; kc += 16) {
        uint32_t a[4];
        ldm_x4(a, &sQ[r0 + lrow][kc + lcol]);
        uint32_t bb[4][4];
#pragma unroll
        for (int nj = 0; nj < 4; nj++)
            ldm_x4(bb[nj], &sK[nj * 16 + lrow][kc + lcol]);
#pragma unroll
        for (int nj = 0; nj < 4; nj++) {
            MMA16816(acc[nj * 2 + 0], a, bb[nj][0], bb[nj][2]);
            MMA16816(acc[nj * 2 + 1], a, bb[nj][1], bb[nj][3]);
        }
    }

    // scale + bias (fragment-order, 4 coalesced uint4 loads)
    {
        const uint4* bp = (const uint4*)(bias_all +
            ((((size_t)type * NHEADS + H) * 4 + ww) * 32 + lane) * 32);
        uint4 q0 = bp[0], q1 = bp[1], q2 = bp[2], q3 = bp[3];
        bf16 barr[32];
        ((uint4*)barr)[0] = q0; ((uint4*)barr)[1] = q1;
        ((uint4*)barr)[2] = q2; ((uint4*)barr)[3] = q3;
#pragma unroll
        for (int nt = 0; nt < 8; nt++) {
#pragma unroll
            for (int sub = 0; sub < 4; sub++)
                acc[nt][sub] = acc[nt][sub] * scale
                             + __bfloat162float(barr[nt * 4 + sub]);
        }
    }

    // softmax
    float mx1 = -1e30f, mx2 = -1e30f;
#pragma unroll
    for (int nt = 0; nt < 8; nt++) {
        mx1 = fmaxf(mx1, fmaxf(acc[nt][0], acc[nt][1]));
        mx2 = fmaxf(mx2, fmaxf(acc[nt][2], acc[nt][3]));
    }
    mx1 = fmaxf(mx1, __shfl_xor_sync(0xffffffffu, mx1, 1));
    mx1 = fmaxf(mx1, __shfl_xor_sync(0xffffffffu, mx1, 2));
    mx2 = fmaxf(mx2, __shfl_xor_sync(0xffffffffu, mx2, 1));
    mx2 = fmaxf(mx2, __shfl_xor_sync(0xffffffffu, mx2, 2));
    float sum1 = 0.f, sum2 = 0.f;
#pragma unroll
    for (int nt = 0; nt < 8; nt++) {
        acc[nt][0] = __expf(acc[nt][0] - mx1);
        acc[nt][1] = __expf(acc[nt][1] - mx1);
        acc[nt][2] = __expf(acc[nt][2] - mx2);
        acc[nt][3] = __expf(acc[nt][3] - mx2);
        sum1 += acc[nt][0] + acc[nt][1];
        sum2 += acc[nt][2] + acc[nt][3];
    }
    sum1 += __shfl_xor_sync(0xffffffffu, sum1, 1);
    sum1 += __shfl_xor_sync(0xffffffffu, sum1, 2);
    sum2 += __shfl_xor_sync(0xffffffffu, sum2, 1);
    sum2 += __shfl_xor_sync(0xffffffffu, sum2, 2);
    float inv1 = 1.0f / sum1, inv2 = 1.0f / sum2;

    // ctx = P V
    float o[4][4] = {};
#pragma unroll
    for (int kc2 = 0; kc2 < 4; kc2++) {
        uint32_t pa[4];
        pa[0] = packbf(acc[2 * kc2][0],     acc[2 * kc2][1]);
        pa[1] = packbf(acc[2 * kc2][2],     acc[2 * kc2][3]);
        pa[2] = packbf(acc[2 * kc2 + 1][0], acc[2 * kc2 + 1][1]);
        pa[3] = packbf(acc[2 * kc2 + 1][2], acc[2 * kc2 + 1][3]);
#pragma unroll
        for (int nj = 0; nj < 2; nj++) {
            uint32_t vb[4];
            ldm_x4t(vb, &sV[kc2 * 16 + lrow][nj * 16 + lcol]);
            MMA16816(o[nj * 2 + 0], pa, vb[0], vb[1]);
            MMA16816(o[nj * 2 + 1], pa, vb[2], vb[3]);
        }
    }
    int row1 = r0 + qr, row2 = r0 + qr + 8;
    if (row1 < NTOK) {
        bf16* dst = O + (size_t)(win * NTOK + row1) * CDIM + H * HDIM + qc * 2;
#pragma unroll
        for (int nt = 0; nt < 4; nt++) {
            __nv_bfloat162 pk;
            pk.x = __float2bfloat16(o[nt][0] * inv1);
            pk.y = __float2bfloat16(o[nt][1] * inv1);
            *(__nv_bfloat162*)(dst + nt * 8) = pk;
        }
    }
    if (row2 < NTOK) {
        bf16* dst = O + (size_t)(win * NTOK + row2) * CDIM + H * HDIM + qc * 2;
#pragma unroll
        for (int nt = 0; nt < 4; nt++) {
            __nv_bfloat162 pk;
            pk.x = __float2bfloat16(o[nt][2] * inv2);
            pk.y = __float2bfloat16(o[nt][3] * inv2);
            *(__nv_bfloat162*)(dst + nt * 8) = pk;
        }
    }
}

// ---------------- launch ----------------
extern "C" void kernel_launch(void* const* d_in, const int* in_sizes, int n_in,
                              void* d_out, int out_size)
{
    const float* hidden  = (const float*)d_in[0];
    const float* ln1_g   = (const float*)d_in[1];
    const float* ln1_b   = (const float*)d_in[2];
    const float* q_w     = (const float*)d_in[3];
    const float* q_b     = (const float*)d_in[4];
    const float* k_w     = (const float*)d_in[5];
    const float* k_b     = (const float*)d_in[6];
    const float* v_w     = (const float*)d_in[7];
    const float* v_b     = (const float*)d_in[8];
    const float* rpb     = (const float*)d_in[9];
    const int*   rpi     = (const int*)  d_in[10];
    const float* proj_w  = (const float*)d_in[11];
    const float* proj_b  = (const float*)d_in[12];
    const float* ln2_g   = (const float*)d_in[13];
    const float* ln2_b   = (const float*)d_in[14];
    const float* fc1_w   = (const float*)d_in[15];
    const float* fc1_b   = (const float*)d_in[16];
    const float* fc2_w   = (const float*)d_in[17];
    const float* fc2_b   = (const float*)d_in[18];
    float* out = (float*)d_out;

    bf16 *p_xw, *p_qkv, *p_ctx, *p_ln2, *p_y1;
    bf16 *p_wqkv, *p_wp, *p_w1, *p_w2, *p_bias;
    float *p_h, *p_bqkv;
    cudaGetSymbolAddress((void**)&p_xw,   g_xw);
    cudaGetSymbolAddress((void**)&p_qkv,  g_qkv);
    cudaGetSymbolAddress((void**)&p_ctx,  g_ctx);
    cudaGetSymbolAddress((void**)&p_h,    g_h);
    cudaGetSymbolAddress((void**)&p_ln2,  g_ln2);
    cudaGetSymbolAddress((void**)&p_y1,   g_y1);
    cudaGetSymbolAddress((void**)&p_wqkv, g_wqkv);
    cudaGetSymbolAddress((void**)&p_bqkv, g_bqkv);
    cudaGetSymbolAddress((void**)&p_wp,   g_wp);
    cudaGetSymbolAddress((void**)&p_w1,   g_w1);
    cudaGetSymbolAddress((void**)&p_w2,   g_w2);
    cudaGetSymbolAddress((void**)&p_bias, g_bias);

    cudaFuncSetAttribute(mma_gemm<0, bf16>,  cudaFuncAttributeMaxDynamicSharedMemorySize, TCSMEM);
    cudaFuncSetAttribute(mma_gemm<1, bf16>,  cudaFuncAttributeMaxDynamicSharedMemorySize, TCSMEM);
    cudaFuncSetAttribute(mma_gemm<2, float>, cudaFuncAttributeMaxDynamicSharedMemorySize, TCSMEM);
    cudaFuncSetAttribute(mma_gemm<3, float>, cudaFuncAttributeMaxDynamicSharedMemorySize, TCSMEM);

    // 0) fused prep: pack qkv + convert weights + bias fragments
    prep_kernel<<<PREP_BLOCKS, 256>>>(
        q_w, k_w, v_w, q_b, k_b, v_b, p_wqkv, p_bqkv,
        proj_w, p_wp, fc1_w, p_w1, fc2_w, p_w2,
        rpb, rpi, p_bias);

    // 1) LN1 + shift-roll + window partition (gather)
    ln_kernel<<<MTOK / 8, 256>>>(hidden, ln1_g, ln1_b, p_xw, 1);

    // 2) fused QKV projection
    mma_gemm<0, bf16><<<dim3(QKVN / GBN, MTOK / GBM), 256, TCSMEM>>>(
        p_xw, p_wqkv, p_bqkv, nullptr, p_qkv, MTOK, QKVN, CDIM);

    // 3) windowed attention (one block per window x head)
    attn_mma_kernel<<<dim3(TOTWIN, NHEADS), 128>>>(p_qkv, p_bias, p_ctx);

    // 4) output projection + window-reverse + roll-back + residual (scatter)
    mma_gemm<2, float><<<dim3(CDIM / GBN, MTOK / GBM), 256, TCSMEM>>>(
        p_ctx, p_wp, proj_b, hidden, p_h, MTOK, CDIM, CDIM);

    // 5) LN2
    ln_kernel<<<MTOK / 8, 256>>>(p_h, ln2_g, ln2_b, p_ln2, 0);

    // 6) fc1 + exact GELU
    mma_gemm<1, bf16><<<dim3(FFNDIM / GBN, MTOK / GBM), 256, TCSMEM>>>(
        p_ln2, p_w1, fc1_b, nullptr, p_y1, MTOK, FFNDIM, CDIM);

    // 7) fc2 + residual -> final output
    mma_gemm<3, float><<<dim3(CDIM / GBN, MTOK / GBM), 256, TCSMEM>>>(
        p_y1, p_w2, fc2_b, p_h, out, MTOK, CDIM, FFNDIM);
}

// round 17
// speedup vs baseline: 1.0163x; 1.0126x over previous
#include <cuda_runtime.h>
#include <cuda_bf16.h>
#include <math.h>
#include <stdint.h>

// ---------------- problem constants ----------------
#define BATCH   8
#define HIMG    56
#define WIMG    56
#define CDIM    384
#define NHEADS  12
#define HDIM    32
#define WIN     7
#define NTOK    49
#define SHIFT_S 3
#define TOTWIN  512
#define MTOK    25088
#define FFNDIM  1536
#define QKVN    1152          // 3*CDIM

typedef __nv_bfloat16 bf16;

// ---------------- scratch (device globals; allocation-free) ----------------
__device__ bf16  g_xw  [MTOK * CDIM];
__device__ bf16  g_qkv [MTOK * QKVN];
__device__ bf16  g_ctx [MTOK * CDIM];
__device__ float g_h   [MTOK * CDIM];
__device__ bf16  g_ln2 [MTOK * CDIM];
__device__ bf16  g_y1  [MTOK * FFNDIM];
__device__ bf16  g_wqkv[CDIM * QKVN];   // [K][N] packed q|k|v
__device__ float g_bqkv[QKVN];
__device__ bf16  g_wp  [CDIM * CDIM];
__device__ bf16  g_w1  [CDIM * FFNDIM];
__device__ bf16  g_w2  [FFNDIM * CDIM];
// bias in mma C-fragment order: [type][head][tb(4)][lane(32)][32]
__device__ bf16  g_bias[4 * NHEADS * 4 * 32 * 32];

// windowed row r <-> original token t (same map both directions)
__device__ __forceinline__ int win_row_to_token(int r) {
    int b    = r / (HIMG * WIMG);
    int rem  = r - b * (HIMG * WIMG);
    int widx = rem / NTOK;
    int tok  = rem - widx * NTOK;
    int wi = widx >> 3, wj = widx & 7;
    int i = tok / WIN, j = tok - i * WIN;
    int sh = wi * WIN + i + SHIFT_S; if (sh >= HIMG) sh -= HIMG;
    int sw = wj * WIN + j + SHIFT_S; if (sw >= WIMG) sw -= WIMG;
    return b * (HIMG * WIMG) + sh * WIMG + sw;
}

// ---------------- fused prep: pack qkv | convert weights | bias frags ------
#define W_PROJ4 (CDIM * CDIM / 4)          // 36864
#define W_FFN4  (CDIM * FFNDIM / 4)        // 147456
#define QKV_W4  (CDIM * QKVN / 4)          // 110592
#define PREP_QKV_ITEMS  (QKV_W4 + QKVN / 4)
#define PREP_W_ITEMS    (W_PROJ4 + 2 * W_FFN4)
#define PREP_QKV_BLOCKS ((PREP_QKV_ITEMS + 255) / 256)
#define PREP_W_BLOCKS   ((PREP_W_ITEMS + 255) / 256)
#define PREP_BIAS_BLOCKS 48
#define PREP_BLOCKS (PREP_QKV_BLOCKS + PREP_W_BLOCKS + PREP_BIAS_BLOCKS)

__global__ void __launch_bounds__(256) prep_kernel(
    const float* __restrict__ qw, const float* __restrict__ kw,
    const float* __restrict__ vw, const float* __restrict__ qb,
    const float* __restrict__ kb, const float* __restrict__ vb,
    bf16* __restrict__ wqkv, float* __restrict__ bqkv,
    const float* __restrict__ pw, bf16* __restrict__ wp,
    const float* __restrict__ w1s, bf16* __restrict__ w1,
    const float* __restrict__ w2s, bf16* __restrict__ w2,
    const float* __restrict__ rpb, const int* __restrict__ rpi,
    bf16* __restrict__ bias_out)
{
    int blk = blockIdx.x;
    if (blk < PREP_QKV_BLOCKS) {
        int i = blk * 256 + threadIdx.x;
        if (i < QKV_W4) {
            int row = i / (QKVN / 4);
            int col = (i % (QKVN / 4)) * 4;
            const float* src = (col < CDIM) ? qw : (col < 2 * CDIM ? kw : vw);
            int c = col - (col < CDIM ? 0 : (col < 2 * CDIM ? CDIM : 2 * CDIM));
            float4 v = *(const float4*)(src + (size_t)row * CDIM + c);
            bf16 o[4] = {__float2bfloat16(v.x), __float2bfloat16(v.y),
                         __float2bfloat16(v.z), __float2bfloat16(v.w)};
            *(uint64_t*)(wqkv + (size_t)i * 4) = *(uint64_t*)o;
        } else if (i < PREP_QKV_ITEMS) {
            int col = (i - QKV_W4) * 4;
            const float* src = (col < CDIM) ? qb : (col < 2 * CDIM ? kb : vb);
            int c = col - (col < CDIM ? 0 : (col < 2 * CDIM ? CDIM : 2 * CDIM));
            *(float4*)(bqkv + col) = *(const float4*)(src + c);
        }
    } else if (blk < PREP_QKV_BLOCKS + PREP_W_BLOCKS) {
        int i = (blk - PREP_QKV_BLOCKS) * 256 + threadIdx.x;
        const float* src; bf16* dst; int idx;
        if (i < W_PROJ4)                 { src = pw;  dst = wp; idx = i; }
        else if (i < W_PROJ4 + W_FFN4)   { src = w1s; dst = w1; idx = i - W_PROJ4; }
        else if (i < PREP_W_ITEMS)       { src = w2s; dst = w2; idx = i - W_PROJ4 - W_FFN4; }
        else return;
        float4 v = ((const float4*)src)[idx];
        bf16 o[4] = {__float2bfloat16(v.x), __float2bfloat16(v.y),
                     __float2bfloat16(v.z), __float2bfloat16(v.w)};
        *(uint64_t*)(dst + (size_t)idx * 4) = *(uint64_t*)o;
    } else {
        int bb = blk - PREP_QKV_BLOCKS - PREP_W_BLOCKS;   // 0..47
        int type = bb / NHEADS, h = bb % NHEADS;
        for (int idx = threadIdx.x; idx < 4096; idx += 256) {
            int tb   = idx >> 10;
            int rem  = idx & 1023;
            int lane = rem >> 5;
            int j    = rem & 31;
            int nt  = j >> 2, sub = j & 3;
            int qr = lane >> 2, qc = lane & 3;
            int n = tb * 16 + qr + ((sub & 2) ? 8 : 0);
            int m = (nt >> 1) * 16 + (nt & 1) * 8 + qc * 2 + (sub & 1);
            float v;
            if (m >= 49)      v = -1e30f;
            else if (n >= 49) v = 0.f;
            else {
                v = rpb[rpi[n * 49 + m] * NHEADS + h];
                int ni = n / 7, nj = n % 7, mi = m / 7, mj = m % 7;
                int cn = ((type & 2) ? (ni < 4 ? 1 : 2) : 0) * 3 + ((type & 1) ? (nj < 4 ? 1 : 2) : 0);
                int cm = ((type & 2) ? (mi < 4 ? 1 : 2) : 0) * 3 + ((type & 1) ? (mj < 4 ? 1 : 2) : 0);
                if (cn != cm) v -= 100.0f;
            }
            bias_out[(((size_t)type * NHEADS + h) * 4096) + idx] = __float2bfloat16(v);
        }
    }
}

// ---------------- LayerNorm: warp-per-row, no barriers ----------------
__global__ void __launch_bounds__(256) ln_kernel(
    const float* __restrict__ x, const float* __restrict__ g,
    const float* __restrict__ b, bf16* __restrict__ out, int permute)
{
    int r = blockIdx.x * 8 + (threadIdx.x >> 5);
    int lane = threadIdx.x & 31;
    int t = permute ? win_row_to_token(r) : r;
    const float4* xi = (const float4*)(x + (size_t)t * CDIM);

    float4 v[3];
    float s = 0.f, ss = 0.f;
#pragma unroll
    for (int j = 0; j < 3; j++) {
        v[j] = xi[lane + 32 * j];
        s  += v[j].x + v[j].y + v[j].z + v[j].w;
        ss += v[j].x * v[j].x + v[j].y * v[j].y
            + v[j].z * v[j].z + v[j].w * v[j].w;
    }
#pragma unroll
    for (int o = 16; o; o >>= 1) {
        s  += __shfl_xor_sync(0xffffffffu, s,  o);
        ss += __shfl_xor_sync(0xffffffffu, ss, o);
    }
    float mu = s * (1.0f / CDIM);
    float var = ss * (1.0f / CDIM) - mu * mu;
    float rstd = rsqrtf(var + 1e-5f);

    bf16* yo = out + (size_t)r * CDIM;
#pragma unroll
    for (int j = 0; j < 3; j++) {
        int c = (lane + 32 * j) * 4;
        float4 gg = *(const float4*)(g + c);
        float4 bb = *(const float4*)(b + c);
        bf16 o[4];
        o[0] = __float2bfloat16((v[j].x - mu) * rstd * gg.x + bb.x);
        o[1] = __float2bfloat16((v[j].y - mu) * rstd * gg.y + bb.y);
        o[2] = __float2bfloat16((v[j].z - mu) * rstd * gg.z + bb.z);
        o[3] = __float2bfloat16((v[j].w - mu) * rstd * gg.w + bb.w);
        *(uint64_t*)(yo + c) = *(uint64_t*)o;
    }
}

// ---------------- mma helpers ----------------
#define CP16(dst, src) \
    asm volatile("cp.async.ca.shared.global [%0], [%1], 16;\n" :: \
        "r"((uint32_t)__cvta_generic_to_shared(dst)), "l"(src))
#define CP16CG(dst, src) \
    asm volatile("cp.async.cg.shared.global [%0], [%1], 16;\n" :: \
        "r"((uint32_t)__cvta_generic_to_shared(dst)), "l"(src))
#define CP_COMMIT()  asm volatile("cp.async.commit_group;\n" ::)
#define CP_WAIT(n)   asm volatile("cp.async.wait_group %0;\n" :: "n"(n))

__device__ __forceinline__ void ldm_x4(uint32_t* r, const void* p) {
    uint32_t a = (uint32_t)__cvta_generic_to_shared(p);
    asm volatile("ldmatrix.sync.aligned.m8n8.x4.shared.b16 {%0,%1,%2,%3},[%4];"
        : "=r"(r[0]), "=r"(r[1]), "=r"(r[2]), "=r"(r[3]) : "r"(a));
}
__device__ __forceinline__ void ldm_x4t(uint32_t* r, const void* p) {
    uint32_t a = (uint32_t)__cvta_generic_to_shared(p);
    asm volatile("ldmatrix.sync.aligned.m8n8.x4.trans.shared.b16 {%0,%1,%2,%3},[%4];"
        : "=r"(r[0]), "=r"(r[1]), "=r"(r[2]), "=r"(r[3]) : "r"(a));
}
#define MMA16816(d, a, b0, b1) \
    asm volatile("mma.sync.aligned.m16n8k16.row.col.f32.bf16.bf16.f32 " \
        "{%0,%1,%2,%3},{%4,%5,%6,%7},{%8,%9},{%0,%1,%2,%3};" \
        : "+f"(d[0]), "+f"(d[1]), "+f"(d[2]), "+f"(d[3]) \
        : "r"(a[0]), "r"(a[1]), "r"(a[2]), "r"(a[3]), "r"(b0), "r"(b1))

__device__ __forceinline__ uint32_t packbf(float lo, float hi) {
    __nv_bfloat162 h = __floats2bfloat162_rn(lo, hi);
    return *(uint32_t*)&h;
}

// ---------------- HMMA bf16 GEMM, 128x128x32, 5-stage, XOR-swizzled --------
// Prefetch issue interleaved between the two kk-halves of the mainloop.
// EPI 0: store  1: exact GELU  2: scatter+residual  3: residual
#define GBM 128
#define GBN 128
#define GBK 32
#define NSTG 5
#define STG_A (GBM * GBK)
#define STG_B (GBK * GBN)
#define TCSMEM (NSTG * (STG_A + STG_B) * 2)   // 81920 bytes

template <int EPI, typename OutT>
__global__ void __launch_bounds__(256) mma_gemm(
    const bf16* __restrict__ A, const bf16* __restrict__ B,
    const float* __restrict__ bias, const float* __restrict__ add,
    OutT* __restrict__ C, int M, int N, int K)
{
    extern __shared__ __align__(16) bf16 sm[];
    bf16* As = sm;
    bf16* Bs = sm + NSTG * STG_A;

    int t = threadIdx.x;
    int m0 = blockIdx.y * GBM, n0 = blockIdx.x * GBN;

    int ar = t >> 2, acw = t & 3;
    int br = t >> 3, bcw = (t & 7) * 2;
    const bf16* Ag = A + (size_t)(m0 + ar) * K + acw * 8;
    const bf16* Bg = B + (size_t)br * N + n0 + bcw * 8;

    int aswz = (ar >> 1) & 3;
    int a_off0 = ar * 32 + ((acw ^ aswz) << 3);
    int a_off1 = (ar + 64) * 32 + ((acw ^ aswz) << 3);
    int b_off0 = br * 128 + (((bcw)     ^ (br & 7)) << 3);
    int b_off1 = br * 128 + (((bcw + 1) ^ (br & 7)) << 3);

    int lane = t & 31, w = t >> 5;
    int m0w = (w >> 1) * 32, nw = (w & 1) * 64;
    int lrow = (lane & 7) + (lane & 8);
    int lcol = (lane & 16) >> 1;

    float acc[2][8][4] = {};

    int nk = K / GBK;
#pragma unroll
    for (int s = 0; s < NSTG - 1; s++) {
        int k0 = s * GBK;
        CP16CG(&As[s * STG_A + a_off0], Ag + k0);
        CP16CG(&As[s * STG_A + a_off1], Ag + (size_t)64 * K + k0);
        CP16CG(&Bs[s * STG_B + b_off0], Bg + (size_t)k0 * N);
        CP16CG(&Bs[s * STG_B + b_off1], Bg + (size_t)k0 * N + 8);
        CP_COMMIT();
    }

    for (int i = 0; i < nk; i++) {
        if (i + 3 < nk)      { CP_WAIT(3); }
        else if (i + 2 < nk) { CP_WAIT(2); }
        else if (i + 1 < nk) { CP_WAIT(1); }
        else                 { CP_WAIT(0); }
        __syncthreads();

        int cs = i % NSTG;
        const bf16* Asc = As + cs * STG_A;
        const bf16* Bsc = Bs + cs * STG_B;

        // ---- kk = 0 half ----
        {
            uint32_t a[2][4], b[4][4];
#pragma unroll
            for (int mi = 0; mi < 2; mi++) {
                int R = m0w + mi * 16 + lrow;
                int cr = lcol >> 3;
                ldm_x4(a[mi], Asc + R * 32 + ((cr ^ ((R >> 1) & 3)) << 3));
            }
#pragma unroll
            for (int nj = 0; nj < 4; nj++) {
                int Kr = lrow;
                int cn = (nw + nj * 16 + lcol) >> 3;
                ldm_x4t(b[nj], Bsc + Kr * 128 + ((cn ^ (Kr & 7)) << 3));
            }
#pragma unroll
            for (int mi = 0; mi < 2; mi++) {
#pragma unroll
                for (int nt = 0; nt < 8; nt++)
                    MMA16816(acc[mi][nt], a[mi],
                             b[nt >> 1][(nt & 1) * 2], b[nt >> 1][(nt & 1) * 2 + 1]);
            }
        }

        // ---- interleaved prefetch of stage i+NSTG-1 ----
        if (i + NSTG - 1 < nk) {
            int st = (i + NSTG - 1) % NSTG;
            int k0 = (i + NSTG - 1) * GBK;
            CP16CG(&As[st * STG_A + a_off0], Ag + k0);
            CP16CG(&As[st * STG_A + a_off1], Ag + (size_t)64 * K + k0);
            CP16CG(&Bs[st * STG_B + b_off0], Bg + (size_t)k0 * N);
            CP16CG(&Bs[st * STG_B + b_off1], Bg + (size_t)k0 * N + 8);
            CP_COMMIT();
        }

        // ---- kk = 16 half ----
        {
            uint32_t a[2][4], b[4][4];
#pragma unroll
            for (int mi = 0; mi < 2; mi++) {
                int R = m0w + mi * 16 + lrow;
                int cr = (16 + lcol) >> 3;
                ldm_x4(a[mi], Asc + R * 32 + ((cr ^ ((R >> 1) & 3)) << 3));
            }
#pragma unroll
            for (int nj = 0; nj < 4; nj++) {
                int Kr = 16 + lrow;
                int cn = (nw + nj * 16 + lcol) >> 3;
                ldm_x4t(b[nj], Bsc + Kr * 128 + ((cn ^ (Kr & 7)) << 3));
            }
#pragma unroll
            for (int mi = 0; mi < 2; mi++) {
#pragma unroll
                for (int nt = 0; nt < 8; nt++)
                    MMA16816(acc[mi][nt], a[mi],
                             b[nt >> 1][(nt & 1) * 2], b[nt >> 1][(nt & 1) * 2 + 1]);
            }
        }
    }

#pragma unroll
    for (int mi = 0; mi < 2; mi++) {
        int rbase = m0 + m0w + mi * 16 + (lane >> 2);
#pragma unroll
        for (int h2 = 0; h2 < 2; h2++) {
            int row = rbase + 8 * h2;
            int orow = (EPI == 2) ? win_row_to_token(row) : row;
#pragma unroll
            for (int nt = 0; nt < 8; nt++) {
                int col = n0 + nw + nt * 8 + (lane & 3) * 2;
                float v0 = acc[mi][nt][2 * h2 + 0] + bias[col];
                float v1 = acc[mi][nt][2 * h2 + 1] + bias[col + 1];
                if (EPI == 1) {
                    v0 = 0.5f * v0 * (1.0f + erff(v0 * 0.7071067811865475f));
                    v1 = 0.5f * v1 * (1.0f + erff(v1 * 0.7071067811865475f));
                } else if (EPI == 2 || EPI == 3) {
                    const float* ap = add + (size_t)orow * N + col;
                    v0 += ap[0];
                    v1 += ap[1];
                }
                OutT* cp = C + (size_t)orow * N + col;
                if (sizeof(OutT) == 2) {
                    __nv_bfloat162 pk;
                    pk.x = __float2bfloat16(v0);
                    pk.y = __float2bfloat16(v1);
                    *(__nv_bfloat162*)cp = pk;
                } else {
                    float2 pk = make_float2(v0, v1);
                    *(float2*)cp = pk;
                }
            }
        }
    }
}

// ---------------- tensor-core window attention ----------------
// grid (TOTWIN, 12): one block per (window, head). 128 threads, 4 warps.
__global__ void __launch_bounds__(128) attn_mma_kernel(
    const bf16* __restrict__ QKV, const bf16* __restrict__ bias_all,
    bf16* __restrict__ O)
{
    __shared__ __align__(16) bf16 sQ[64][40];
    __shared__ __align__(16) bf16 sK[64][40];
    __shared__ __align__(16) bf16 sV[64][40];

    int win = blockIdx.x, H = blockIdx.y, t = threadIdx.x;
    int widx = win & 63;
    int type = (((widx >> 3) == 7) ? 2 : 0) + (((widx & 7) == 7) ? 1 : 0);

    int lane = t & 31, ww = t >> 5;
    int r0 = ww * 16;
    int lrow = (lane & 7) + (lane & 8);
    int lcol = (lane & 16) >> 1;
    int qr = lane >> 2, qc = lane & 3;
    const float scale = 0.17677669529663687f;

    int lr = t >> 1, lc2 = (t & 1) * 2;

    if (lr < 49) {
        const bf16* src = QKV + (size_t)(win * NTOK + lr) * QKVN + H * HDIM + lc2 * 8;
        CP16CG(&sQ[lr][lc2 * 8], src);
        CP16CG(&sQ[lr][lc2 * 8 + 8], src + 8);
        CP16CG(&sK[lr][lc2 * 8], src + CDIM);
        CP16CG(&sK[lr][lc2 * 8 + 8], src + CDIM + 8);
        CP16CG(&sV[lr][lc2 * 8], src + 2 * CDIM);
        CP16CG(&sV[lr][lc2 * 8 + 8], src + 2 * CDIM + 8);
    }
    CP_COMMIT();

    for (int i = t; i < 15 * 40; i += 128) {
        int row = 49 + i / 40, col = i % 40;
        sK[row][col] = __float2bfloat16(0.f);
        sV[row][col] = __float2bfloat16(0.f);
    }

    CP_WAIT(0);
    __syncthreads();

    float acc[8][4] = {};
#pragma unroll
    for (int kc = 0; kc < 32; kc += 16) {
        uint32_t a[4];
        ldm_x4(a, &sQ[r0 + lrow][kc + lcol]);
        uint32_t bb[4][4];
#pragma unroll
        for (int nj = 0; nj < 4; nj++)
            ldm_x4(bb[nj], &sK[nj * 16 + lrow][kc + lcol]);
#pragma unroll
        for (int nj = 0; nj < 4; nj++) {
            MMA16816(acc[nj * 2 + 0], a, bb[nj][0], bb[nj][2]);
            MMA16816(acc[nj * 2 + 1], a, bb[nj][1], bb[nj][3]);
        }
    }

    {
        const uint4* bp = (const uint4*)(bias_all +
            ((((size_t)type * NHEADS + H) * 4 + ww) * 32 + lane) * 32);
        uint4 q0 = bp[0], q1 = bp[1], q2 = bp[2], q3 = bp[3];
        bf16 barr[32];
        ((uint4*)barr)[0] = q0; ((uint4*)barr)[1] = q1;
        ((uint4*)barr)[2] = q2; ((uint4*)barr)[3] = q3;
#pragma unroll
        for (int nt = 0; nt < 8; nt++) {
#pragma unroll
            for (int sub = 0; sub < 4; sub++)
                acc[nt][sub] = acc[nt][sub] * scale
                             + __bfloat162float(barr[nt * 4 + sub]);
        }
    }

    float mx1 = -1e30f, mx2 = -1e30f;
#pragma unroll
    for (int nt = 0; nt < 8; nt++) {
        mx1 = fmaxf(mx1, fmaxf(acc[nt][0], acc[nt][1]));
        mx2 = fmaxf(mx2, fmaxf(acc[nt][2], acc[nt][3]));
    }
    mx1 = fmaxf(mx1, __shfl_xor_sync(0xffffffffu, mx1, 1));
    mx1 = fmaxf(mx1, __shfl_xor_sync(0xffffffffu, mx1, 2));
    mx2 = fmaxf(mx2, __shfl_xor_sync(0xffffffffu, mx2, 1));
    mx2 = fmaxf(mx2, __shfl_xor_sync(0xffffffffu, mx2, 2));
    float sum1 = 0.f, sum2 = 0.f;
#pragma unroll
    for (int nt = 0; nt < 8; nt++) {
        acc[nt][0] = __expf(acc[nt][0] - mx1);
        acc[nt][1] = __expf(acc[nt][1] - mx1);
        acc[nt][2] = __expf(acc[nt][2] - mx2);
        acc[nt][3] = __expf(acc[nt][3] - mx2);
        sum1 += acc[nt][0] + acc[nt][1];
        sum2 += acc[nt][2] + acc[nt][3];
    }
    sum1 += __shfl_xor_sync(0xffffffffu, sum1, 1);
    sum1 += __shfl_xor_sync(0xffffffffu, sum1, 2);
    sum2 += __shfl_xor_sync(0xffffffffu, sum2, 1);
    sum2 += __shfl_xor_sync(0xffffffffu, sum2, 2);
    float inv1 = 1.0f / sum1, inv2 = 1.0f / sum2;

    float o[4][4] = {};
#pragma unroll
    for (int kc2 = 0; kc2 < 4; kc2++) {
        uint32_t pa[4];
        pa[0] = packbf(acc[2 * kc2][0],     acc[2 * kc2][1]);
        pa[1] = packbf(acc[2 * kc2][2],     acc[2 * kc2][3]);
        pa[2] = packbf(acc[2 * kc2 + 1][0], acc[2 * kc2 + 1][1]);
        pa[3] = packbf(acc[2 * kc2 + 1][2], acc[2 * kc2 + 1][3]);
#pragma unroll
        for (int nj = 0; nj < 2; nj++) {
            uint32_t vb[4];
            ldm_x4t(vb, &sV[kc2 * 16 + lrow][nj * 16 + lcol]);
            MMA16816(o[nj * 2 + 0], pa, vb[0], vb[1]);
            MMA16816(o[nj * 2 + 1], pa, vb[2], vb[3]);
        }
    }
    int row1 = r0 + qr, row2 = r0 + qr + 8;
    if (row1 < NTOK) {
        bf16* dst = O + (size_t)(win * NTOK + row1) * CDIM + H * HDIM + qc * 2;
#pragma unroll
        for (int nt = 0; nt < 4; nt++) {
            __nv_bfloat162 pk;
            pk.x = __float2bfloat16(o[nt][0] * inv1);
            pk.y = __float2bfloat16(o[nt][1] * inv1);
            *(__nv_bfloat162*)(dst + nt * 8) = pk;
        }
    }
    if (row2 < NTOK) {
        bf16* dst = O + (size_t)(win * NTOK + row2) * CDIM + H * HDIM + qc * 2;
#pragma unroll
        for (int nt = 0; nt < 4; nt++) {
            __nv_bfloat162 pk;
            pk.x = __float2bfloat16(o[nt][2] * inv2);
            pk.y = __float2bfloat16(o[nt][3] * inv2);
            *(__nv_bfloat162*)(dst + nt * 8) = pk;
        }
    }
}

// ---------------- launch ----------------
extern "C" void kernel_launch(void* const* d_in, const int* in_sizes, int n_in,
                              void* d_out, int out_size)
{
    const float* hidden  = (const float*)d_in[0];
    const float* ln1_g   = (const float*)d_in[1];
    const float* ln1_b   = (const float*)d_in[2];
    const float* q_w     = (const float*)d_in[3];
    const float* q_b     = (const float*)d_in[4];
    const float* k_w     = (const float*)d_in[5];
    const float* k_b     = (const float*)d_in[6];
    const float* v_w     = (const float*)d_in[7];
    const float* v_b     = (const float*)d_in[8];
    const float* rpb     = (const float*)d_in[9];
    const int*   rpi     = (const int*)  d_in[10];
    const float* proj_w  = (const float*)d_in[11];
    const float* proj_b  = (const float*)d_in[12];
    const float* ln2_g   = (const float*)d_in[13];
    const float* ln2_b   = (const float*)d_in[14];
    const float* fc1_w   = (const float*)d_in[15];
    const float* fc1_b   = (const float*)d_in[16];
    const float* fc2_w   = (const float*)d_in[17];
    const float* fc2_b   = (const float*)d_in[18];
    float* out = (float*)d_out;

    bf16 *p_xw, *p_qkv, *p_ctx, *p_ln2, *p_y1;
    bf16 *p_wqkv, *p_wp, *p_w1, *p_w2, *p_bias;
    float *p_h, *p_bqkv;
    cudaGetSymbolAddress((void**)&p_xw,   g_xw);
    cudaGetSymbolAddress((void**)&p_qkv,  g_qkv);
    cudaGetSymbolAddress((void**)&p_ctx,  g_ctx);
    cudaGetSymbolAddress((void**)&p_h,    g_h);
    cudaGetSymbolAddress((void**)&p_ln2,  g_ln2);
    cudaGetSymbolAddress((void**)&p_y1,   g_y1);
    cudaGetSymbolAddress((void**)&p_wqkv, g_wqkv);
    cudaGetSymbolAddress((void**)&p_bqkv, g_bqkv);
    cudaGetSymbolAddress((void**)&p_wp,   g_wp);
    cudaGetSymbolAddress((void**)&p_w1,   g_w1);
    cudaGetSymbolAddress((void**)&p_w2,   g_w2);
    cudaGetSymbolAddress((void**)&p_bias, g_bias);

    cudaFuncSetAttribute(mma_gemm<0, bf16>,  cudaFuncAttributeMaxDynamicSharedMemorySize, TCSMEM);
    cudaFuncSetAttribute(mma_gemm<1, bf16>,  cudaFuncAttributeMaxDynamicSharedMemorySize, TCSMEM);
    cudaFuncSetAttribute(mma_gemm<2, float>, cudaFuncAttributeMaxDynamicSharedMemorySize, TCSMEM);
    cudaFuncSetAttribute(mma_gemm<3, float>, cudaFuncAttributeMaxDynamicSharedMemorySize, TCSMEM);

    // 0) fused prep: pack qkv + convert weights + bias fragments
    prep_kernel<<<PREP_BLOCKS, 256>>>(
        q_w, k_w, v_w, q_b, k_b, v_b, p_wqkv, p_bqkv,
        proj_w, p_wp, fc1_w, p_w1, fc2_w, p_w2,
        rpb, rpi, p_bias);

    // 1) LN1 + shift-roll + window partition (gather)
    ln_kernel<<<MTOK / 8, 256>>>(hidden, ln1_g, ln1_b, p_xw, 1);

    // 2) fused QKV projection
    mma_gemm<0, bf16><<<dim3(QKVN / GBN, MTOK / GBM), 256, TCSMEM>>>(
        p_xw, p_wqkv, p_bqkv, nullptr, p_qkv, MTOK, QKVN, CDIM);

    // 3) windowed attention (one block per window x head)
    attn_mma_kernel<<<dim3(TOTWIN, NHEADS), 128>>>(p_qkv, p_bias, p_ctx);

    // 4) output projection + window-reverse + roll-back + residual (scatter)
    mma_gemm<2, float><<<dim3(CDIM / GBN, MTOK / GBM), 256, TCSMEM>>>(
        p_ctx, p_wp, proj_b, hidden, p_h, MTOK, CDIM, CDIM);

    // 5) LN2
    ln_kernel<<<MTOK / 8, 256>>>(p_h, ln2_g, ln2_b, p_ln2, 0);

    // 6) fc1 + exact GELU
    mma_gemm<1, bf16><<<dim3(FFNDIM / GBN, MTOK / GBM), 256, TCSMEM>>>(
        p_ln2, p_w1, fc1_b, nullptr, p_y1, MTOK, FFNDIM, CDIM);

    // 7) fc2 + residual -> final output
    mma_gemm<3, float><<<dim3(CDIM / GBN, MTOK / GBM), 256, TCSMEM>>>(
        p_y1, p_w2, fc2_b, p_h, out, MTOK, CDIM, FFNDIM);
}